// round 13
// baseline (speedup 1.0000x reference)
#include <cuda_runtime.h>
#include <cuda_bf16.h>
#include <cstdint>

// Problem constants (shapes fixed by the dataset)
#define N_NODES_MAX 100000
#define D 64
#define OUT 64
#define LN_EPS 1e-5f

// Scratch (device globals — no allocs allowed)
__device__ __align__(16) float g_nsum[N_NODES_MAX * D];       // scatter accumulator
__device__ __align__(16) float g_partial[N_NODES_MAX * OUT];  // x@W1 + b

#define NTHR 256
#define TILE1 64     // gemm1 role: nodes per tile
#define TILE2 128    // gemm2: nodes per tile

// ---------------------------------------------------------------------------
// Kernel 1 (fused, resource-bounded): bid%4==0 -> gemm1 role, else scatter.
// Uniform footprint: 32KB dyn smem, <=42 regs (launch_bounds 256,6)
//   -> ~6 blocks/SM for BOTH roles; scatter keeps 48 warps/SM (LTS-saturating
//      with unroll-4 MLP), gemm1's FMA work hides under the scatter.
// gemm1 role: partial[tile] = x[tile] @ W[0:64] + b   (TILE1=64, K=64, 4x4)
// scatter role: unroll-4 chunked red.global.add.v4.f32 (R12-proven)
// ---------------------------------------------------------------------------
__global__ void __launch_bounds__(NTHR, 6) fused_scatter_gemm1_kernel(
    const float4* __restrict__ x4,
    const void*   __restrict__ ei_raw,
    const float4* __restrict__ W4,
    const float*  __restrict__ b,
    int n_edges, int n_nodes, int n_tiles, int n_scat_blocks) {

    extern __shared__ char smem_raw[];
    const int bid = blockIdx.x;
    const int tid = threadIdx.x;

    if ((bid & 3) == 0) {
        // ---------------- gemm1 role ----------------
        const int tile = bid >> 2;               // < n_tiles by construction
        float* Ash = reinterpret_cast<float*>(smem_raw);               // [64][64] 16KB
        float* Wsh = reinterpret_cast<float*>(smem_raw + 64 * 64 * 4); // [64][64] 16KB

        const int tx = tid & 15;   // outs 4tx..4tx+3
        const int ty = tid >> 4;   // nodes 4ty..4ty+3
        const int node_base = tile * TILE1;

        // stage W1 = W rows 0..63 (first 1024 float4s)
        {
            float4* Wsh4 = reinterpret_cast<float4*>(Wsh);
            #pragma unroll
            for (int i = tid; i < 64 * 64 / 4; i += NTHR) Wsh4[i] = W4[i];
        }
        // stage A transposed: Ash[k*64+n] = x[node_base+n][k], k<64
        {
            #pragma unroll
            for (int it = 0; it < 4; it++) {
                int idx = it * NTHR + tid;    // 0..1023
                int n = idx & 63;
                int r = idx >> 6;             // k-quad 0..15
                int gn = node_base + n;
                float4 v = make_float4(0.f, 0.f, 0.f, 0.f);
                if (gn < n_nodes) v = x4[(long long)gn * 16 + r];
                int k0 = 4 * r;
                Ash[(k0 + 0) * 64 + n] = v.x;
                Ash[(k0 + 1) * 64 + n] = v.y;
                Ash[(k0 + 2) * 64 + n] = v.z;
                Ash[(k0 + 3) * 64 + n] = v.w;
            }
        }
        __syncthreads();

        // acc[i][j]: node-pair i (nodes 2i,2i+1 of this thread's 4) x out j
        unsigned long long acc[2][4];
        #pragma unroll
        for (int i = 0; i < 2; i++)
            #pragma unroll
            for (int j = 0; j < 4; j++) acc[i][j] = 0ull;

        const unsigned long long* ab =
            reinterpret_cast<const unsigned long long*>(Ash + 4 * ty);
        const float* wb = Wsh + 4 * tx;

        #pragma unroll 4
        for (int k = 0; k < 64; k++) {
            ulonglong2 a01 = *reinterpret_cast<const ulonglong2*>(ab + k * 32);
            float4 wv = *reinterpret_cast<const float4*>(wb + k * 64);
            unsigned long long wd[4];
            asm("mov.b64 %0, {%1, %1};" : "=l"(wd[0]) : "f"(wv.x));
            asm("mov.b64 %0, {%1, %1};" : "=l"(wd[1]) : "f"(wv.y));
            asm("mov.b64 %0, {%1, %1};" : "=l"(wd[2]) : "f"(wv.z));
            asm("mov.b64 %0, {%1, %1};" : "=l"(wd[3]) : "f"(wv.w));
            unsigned long long ap[2] = {a01.x, a01.y};
            #pragma unroll
            for (int i = 0; i < 2; i++) {
                asm("fma.rn.f32x2 %0, %1, %2, %0;" : "+l"(acc[i][0]) : "l"(ap[i]), "l"(wd[0]));
                asm("fma.rn.f32x2 %0, %1, %2, %0;" : "+l"(acc[i][1]) : "l"(ap[i]), "l"(wd[1]));
                asm("fma.rn.f32x2 %0, %1, %2, %0;" : "+l"(acc[i][2]) : "l"(ap[i]), "l"(wd[2]));
                asm("fma.rn.f32x2 %0, %1, %2, %0;" : "+l"(acc[i][3]) : "l"(ap[i]), "l"(wd[3]));
            }
        }

        // epilogue: + bias, store partial
        const float4 bj = reinterpret_cast<const float4*>(b)[tx];
        const float bja[4] = {bj.x, bj.y, bj.z, bj.w};
        float4* partial4 = reinterpret_cast<float4*>(g_partial);

        #pragma unroll
        for (int i = 0; i < 2; i++) {
            float lo[4], hi[4];
            #pragma unroll
            for (int j = 0; j < 4; j++) {
                lo[j] = __uint_as_float((unsigned)(acc[i][j] & 0xffffffffull)) + bja[j];
                hi[j] = __uint_as_float((unsigned)(acc[i][j] >> 32))           + bja[j];
            }
            int gn0 = node_base + 4 * ty + 2 * i;
            if (gn0 < n_nodes)
                partial4[(long long)gn0 * 16 + tx] = make_float4(lo[0], lo[1], lo[2], lo[3]);
            if (gn0 + 1 < n_nodes)
                partial4[(long long)(gn0 + 1) * 16 + tx] = make_float4(hi[0], hi[1], hi[2], hi[3]);
        }
    } else {
        // ---------------- scatter role (R12-proven unroll-4) ----------------
        const long long* ei64 = reinterpret_cast<const long long*>(ei_raw);
        const int*       ei32 = reinterpret_cast<const int*>(ei_raw);

        int bad = 0;
        {
            int nw = n_edges / 2;
            if (nw > 256) nw = 256;
            if (tid < nw) {
                long long v = ei64[tid];
                bad = (v < 0 || v >= (long long)n_nodes) ? 1 : 0;
            }
        }
        const int is64 = !__syncthreads_or(bad);

        // dense scatter-block index (gemm blocks before bid = (bid+3)>>2)
        const int sbid = bid - ((bid + 3) >> 2);

        const int t   = sbid * NTHR + tid;
        const int sub = t & 15;
        const int grp = t >> 4;
        const int ngrp = (n_scat_blocks * NTHR) >> 4;
        float4* __restrict__ nsum4 = reinterpret_cast<float4*>(g_nsum);

        const int nchunks = n_edges >> 2;

        if (is64) {
            for (int c = grp; c < nchunks; c += ngrp) {
                const int e = c * 4;
                longlong2 r01 = *reinterpret_cast<const longlong2*>(ei64 + e);
                longlong2 r23 = *reinterpret_cast<const longlong2*>(ei64 + e + 2);
                longlong2 c01 = *reinterpret_cast<const longlong2*>(ei64 + n_edges + e);
                longlong2 c23 = *reinterpret_cast<const longlong2*>(ei64 + n_edges + e + 2);
                float4 v0 = x4[r01.x * 16 + sub];
                float4 v1 = x4[r01.y * 16 + sub];
                float4 v2 = x4[r23.x * 16 + sub];
                float4 v3 = x4[r23.y * 16 + sub];
                asm volatile("red.global.add.v4.f32 [%0], {%1, %2, %3, %4};"
                             :: "l"(&nsum4[c01.x * 16 + sub]),
                                "f"(v0.x), "f"(v0.y), "f"(v0.z), "f"(v0.w) : "memory");
                asm volatile("red.global.add.v4.f32 [%0], {%1, %2, %3, %4};"
                             :: "l"(&nsum4[c01.y * 16 + sub]),
                                "f"(v1.x), "f"(v1.y), "f"(v1.z), "f"(v1.w) : "memory");
                asm volatile("red.global.add.v4.f32 [%0], {%1, %2, %3, %4};"
                             :: "l"(&nsum4[c23.x * 16 + sub]),
                                "f"(v2.x), "f"(v2.y), "f"(v2.z), "f"(v2.w) : "memory");
                asm volatile("red.global.add.v4.f32 [%0], {%1, %2, %3, %4};"
                             :: "l"(&nsum4[c23.y * 16 + sub]),
                                "f"(v3.x), "f"(v3.y), "f"(v3.z), "f"(v3.w) : "memory");
            }
            for (int e = (nchunks << 2) + grp; e < n_edges; e += ngrp) {
                long long row = ei64[e];
                long long col = ei64[n_edges + e];
                float4 v = x4[row * 16 + sub];
                asm volatile("red.global.add.v4.f32 [%0], {%1, %2, %3, %4};"
                             :: "l"(&nsum4[col * 16 + sub]),
                                "f"(v.x), "f"(v.y), "f"(v.z), "f"(v.w) : "memory");
            }
        } else {
            for (int c = grp; c < nchunks; c += ngrp) {
                const int e = c * 4;
                int4 rr = *reinterpret_cast<const int4*>(ei32 + e);
                int4 cc = *reinterpret_cast<const int4*>(ei32 + n_edges + e);
                float4 v0 = x4[(long long)rr.x * 16 + sub];
                float4 v1 = x4[(long long)rr.y * 16 + sub];
                float4 v2 = x4[(long long)rr.z * 16 + sub];
                float4 v3 = x4[(long long)rr.w * 16 + sub];
                asm volatile("red.global.add.v4.f32 [%0], {%1, %2, %3, %4};"
                             :: "l"(&nsum4[(long long)cc.x * 16 + sub]),
                                "f"(v0.x), "f"(v0.y), "f"(v0.z), "f"(v0.w) : "memory");
                asm volatile("red.global.add.v4.f32 [%0], {%1, %2, %3, %4};"
                             :: "l"(&nsum4[(long long)cc.y * 16 + sub]),
                                "f"(v1.x), "f"(v1.y), "f"(v1.z), "f"(v1.w) : "memory");
                asm volatile("red.global.add.v4.f32 [%0], {%1, %2, %3, %4};"
                             :: "l"(&nsum4[(long long)cc.z * 16 + sub]),
                                "f"(v2.x), "f"(v2.y), "f"(v2.z), "f"(v2.w) : "memory");
                asm volatile("red.global.add.v4.f32 [%0], {%1, %2, %3, %4};"
                             :: "l"(&nsum4[(long long)cc.w * 16 + sub]),
                                "f"(v3.x), "f"(v3.y), "f"(v3.z), "f"(v3.w) : "memory");
            }
            for (int e = (nchunks << 2) + grp; e < n_edges; e += ngrp) {
                long long row = ei32[e];
                long long col = ei32[n_edges + e];
                float4 v = x4[row * 16 + sub];
                asm volatile("red.global.add.v4.f32 [%0], {%1, %2, %3, %4};"
                             :: "l"(&nsum4[col * 16 + sub]),
                                "f"(v.x), "f"(v.y), "f"(v.z), "f"(v.w) : "memory");
            }
        }
    }
}

// ---------------------------------------------------------------------------
// Kernel 2: h = nsum @ W2 + partial, then LayerNorm.  K=64.
// (validated in R10/R11, ~34 us)
// ---------------------------------------------------------------------------
__global__ void __launch_bounds__(NTHR, 3) gemm2_ln_kernel(
    const float4* __restrict__ W4,
    const float*  __restrict__ gamma,
    const float*  __restrict__ beta,
    float4* __restrict__ out4,
    int n_nodes) {

    extern __shared__ char smem_raw[];
    float* Ash = reinterpret_cast<float*>(smem_raw);   // [64][128] = 32KB

    const int tid = threadIdx.x;
    const int tx  = tid & 15;
    const int ty  = tid >> 4;
    const int node_base = blockIdx.x * TILE2;

    {
        const float4* nsum4 = reinterpret_cast<const float4*>(g_nsum);
        #pragma unroll
        for (int it = 0; it < 8; it++) {
            int idx = it * NTHR + tid;
            int n = idx & 127;
            int r = idx >> 7;
            int gn = node_base + n;
            float4 v = make_float4(0.f, 0.f, 0.f, 0.f);
            if (gn < n_nodes) v = nsum4[(long long)gn * 16 + r];
            int k0 = 4 * r;
            Ash[(k0 + 0) * 128 + n] = v.x;
            Ash[(k0 + 1) * 128 + n] = v.y;
            Ash[(k0 + 2) * 128 + n] = v.z;
            Ash[(k0 + 3) * 128 + n] = v.w;
        }
    }
    __syncthreads();

    unsigned long long acc[4][4];
    #pragma unroll
    for (int i = 0; i < 4; i++)
        #pragma unroll
        for (int j = 0; j < 4; j++) acc[i][j] = 0ull;

    const unsigned long long* ab =
        reinterpret_cast<const unsigned long long*>(Ash + 8 * ty);
    const float4* wg = W4 + 64 * 16 + tx;   // W rows 64..127

    #pragma unroll 8
    for (int k = 0; k < 64; k++) {
        ulonglong2 a01 = *reinterpret_cast<const ulonglong2*>(ab + k * 64);
        ulonglong2 a23 = *reinterpret_cast<const ulonglong2*>(ab + k * 64 + 2);
        float4 wv = __ldg(wg + k * 16);
        unsigned long long wd[4];
        asm("mov.b64 %0, {%1, %1};" : "=l"(wd[0]) : "f"(wv.x));
        asm("mov.b64 %0, {%1, %1};" : "=l"(wd[1]) : "f"(wv.y));
        asm("mov.b64 %0, {%1, %1};" : "=l"(wd[2]) : "f"(wv.z));
        asm("mov.b64 %0, {%1, %1};" : "=l"(wd[3]) : "f"(wv.w));
        unsigned long long ap[4] = {a01.x, a01.y, a23.x, a23.y};
        #pragma unroll
        for (int i = 0; i < 4; i++) {
            asm("fma.rn.f32x2 %0, %1, %2, %0;" : "+l"(acc[i][0]) : "l"(ap[i]), "l"(wd[0]));
            asm("fma.rn.f32x2 %0, %1, %2, %0;" : "+l"(acc[i][1]) : "l"(ap[i]), "l"(wd[1]));
            asm("fma.rn.f32x2 %0, %1, %2, %0;" : "+l"(acc[i][2]) : "l"(ap[i]), "l"(wd[2]));
            asm("fma.rn.f32x2 %0, %1, %2, %0;" : "+l"(acc[i][3]) : "l"(ap[i]), "l"(wd[3]));
        }
    }

    const float4 gj = reinterpret_cast<const float4*>(gamma)[tx];
    const float4 ej = reinterpret_cast<const float4*>(beta)[tx];
    const float4* partial4 = reinterpret_cast<const float4*>(g_partial);

    float val[8][4];
    #pragma unroll
    for (int i = 0; i < 4; i++) {
        int gn0 = node_base + 8 * ty + 2 * i;
        float4 p0 = (gn0     < n_nodes) ? partial4[(long long)gn0 * 16 + tx]
                                        : make_float4(0.f, 0.f, 0.f, 0.f);
        float4 p1 = (gn0 + 1 < n_nodes) ? partial4[(long long)(gn0 + 1) * 16 + tx]
                                        : make_float4(0.f, 0.f, 0.f, 0.f);
        const float pa0[4] = {p0.x, p0.y, p0.z, p0.w};
        const float pa1[4] = {p1.x, p1.y, p1.z, p1.w};
        #pragma unroll
        for (int j = 0; j < 4; j++) {
            val[2 * i][j]     = __uint_as_float((unsigned)(acc[i][j] & 0xffffffffull)) + pa0[j];
            val[2 * i + 1][j] = __uint_as_float((unsigned)(acc[i][j] >> 32))           + pa1[j];
        }
    }

    float s[8], ss[8];
    #pragma unroll
    for (int i = 0; i < 8; i++) {
        s[i]  = val[i][0] + val[i][1] + val[i][2] + val[i][3];
        ss[i] = val[i][0] * val[i][0] + val[i][1] * val[i][1]
              + val[i][2] * val[i][2] + val[i][3] * val[i][3];
    }
    #pragma unroll
    for (int m = 1; m < 16; m <<= 1) {
        #pragma unroll
        for (int i = 0; i < 8; i++) {
            s[i]  += __shfl_xor_sync(0xFFFFFFFFu, s[i],  m);
            ss[i] += __shfl_xor_sync(0xFFFFFFFFu, ss[i], m);
        }
    }

    const float inv64 = 1.0f / 64.0f;
    #pragma unroll
    for (int i = 0; i < 8; i++) {
        float mu  = s[i] * inv64;
        float var = ss[i] * inv64 - mu * mu;
        float rs  = rsqrtf(var + LN_EPS);
        int gn = node_base + 8 * ty + i;
        if (gn < n_nodes) {
            float4 o;
            o.x = (val[i][0] - mu) * rs * gj.x + ej.x;
            o.y = (val[i][1] - mu) * rs * gj.y + ej.y;
            o.z = (val[i][2] - mu) * rs * gj.z + ej.z;
            o.w = (val[i][3] - mu) * rs * gj.w + ej.w;
            out4[(long long)gn * 16 + tx] = o;
        }
    }
}

// ---------------------------------------------------------------------------
// launch
// ---------------------------------------------------------------------------
extern "C" void kernel_launch(void* const* d_in, const int* in_sizes, int n_in,
                              void* d_out, int out_size) {
    const float* x     = (const float*)d_in[0];
    const void*  ei    = d_in[1];
    const float* W     = (const float*)d_in[2];
    const float* b     = (const float*)d_in[3];
    const float* gamma = (const float*)d_in[4];
    const float* beta  = (const float*)d_in[5];
    float* out = (float*)d_out;

    const int n_nodes = in_sizes[0] / D;      // 100000
    const int n_edges = in_sizes[1] / 2;      // 1000000

    static void* nsum_ptr = nullptr;
    if (!nsum_ptr) {
        cudaGetSymbolAddress(&nsum_ptr, g_nsum);
        cudaFuncSetAttribute(fused_scatter_gemm1_kernel,
                             cudaFuncAttributeMaxDynamicSharedMemorySize, 32768);
        cudaFuncSetAttribute(gemm2_ln_kernel,
                             cudaFuncAttributeMaxDynamicSharedMemorySize, 32768);
    }

    // 0: zero accumulator via memset node
    cudaMemsetAsync(nsum_ptr, 0, (size_t)n_nodes * D * sizeof(float), 0);

    // 1: fused scatter + x@W1 (role mix 3:1 per wave, 32KB/42reg uniform)
    const int n_tiles1 = (n_nodes + TILE1 - 1) / TILE1;    // 1563
    const int grid = 4 * n_tiles1;                         // 6252
    const int n_scat_blocks = grid - n_tiles1;             // 4689
    fused_scatter_gemm1_kernel<<<grid, NTHR, 32768>>>(
        (const float4*)x, ei, (const float4*)W, b,
        n_edges, n_nodes, n_tiles1, n_scat_blocks);

    // 2: nsum@W2 + partial, LayerNorm
    const int n_tiles2 = (n_nodes + TILE2 - 1) / TILE2;    // 782
    gemm2_ln_kernel<<<n_tiles2, NTHR, 32768>>>(
        (const float4*)W, gamma, beta, (float4*)out, n_nodes);
}

// round 15
// speedup vs baseline: 1.0794x; 1.0794x over previous
#include <cuda_runtime.h>
#include <cuda_bf16.h>
#include <cstdint>

#define N_NODES_MAX 100000
#define D 64
#define OUT 64
#define LN_EPS 1e-5f

// Scratch: neighbor_sum accumulator [N, D]
__device__ __align__(16) float g_nsum[N_NODES_MAX * D];

// ---------------------------------------------------------------------------
// Kernel 1: scatter-add (R12-proven, unroll-4 MLP, red.global.add.v4.f32)
// ---------------------------------------------------------------------------
__global__ void __launch_bounds__(256) scatter_kernel(
    const float4* __restrict__ x4,
    const void* __restrict__ ei_raw,
    int n_edges, int n_nodes) {

    const long long* ei64 = reinterpret_cast<const long long*>(ei_raw);
    const int*       ei32 = reinterpret_cast<const int*>(ei_raw);

    int bad = 0;
    {
        int nw = n_edges / 2;
        if (nw > 256) nw = 256;
        if ((int)threadIdx.x < nw) {
            long long v = ei64[threadIdx.x];
            bad = (v < 0 || v >= (long long)n_nodes) ? 1 : 0;
        }
    }
    const int is64 = !__syncthreads_or(bad);

    const int t   = blockIdx.x * blockDim.x + threadIdx.x;
    const int sub = t & 15;
    const int grp = t >> 4;
    const int ngrp = (gridDim.x * blockDim.x) >> 4;
    float4* __restrict__ nsum4 = reinterpret_cast<float4*>(g_nsum);
    const int nchunks = n_edges >> 2;

    if (is64) {
        for (int c = grp; c < nchunks; c += ngrp) {
            const int e = c * 4;
            longlong2 r01 = *reinterpret_cast<const longlong2*>(ei64 + e);
            longlong2 r23 = *reinterpret_cast<const longlong2*>(ei64 + e + 2);
            longlong2 c01 = *reinterpret_cast<const longlong2*>(ei64 + n_edges + e);
            longlong2 c23 = *reinterpret_cast<const longlong2*>(ei64 + n_edges + e + 2);
            float4 v0 = x4[r01.x * 16 + sub];
            float4 v1 = x4[r01.y * 16 + sub];
            float4 v2 = x4[r23.x * 16 + sub];
            float4 v3 = x4[r23.y * 16 + sub];
            asm volatile("red.global.add.v4.f32 [%0], {%1, %2, %3, %4};"
                         :: "l"(&nsum4[c01.x * 16 + sub]),
                            "f"(v0.x), "f"(v0.y), "f"(v0.z), "f"(v0.w) : "memory");
            asm volatile("red.global.add.v4.f32 [%0], {%1, %2, %3, %4};"
                         :: "l"(&nsum4[c01.y * 16 + sub]),
                            "f"(v1.x), "f"(v1.y), "f"(v1.z), "f"(v1.w) : "memory");
            asm volatile("red.global.add.v4.f32 [%0], {%1, %2, %3, %4};"
                         :: "l"(&nsum4[c23.x * 16 + sub]),
                            "f"(v2.x), "f"(v2.y), "f"(v2.z), "f"(v2.w) : "memory");
            asm volatile("red.global.add.v4.f32 [%0], {%1, %2, %3, %4};"
                         :: "l"(&nsum4[c23.y * 16 + sub]),
                            "f"(v3.x), "f"(v3.y), "f"(v3.z), "f"(v3.w) : "memory");
        }
        for (int e = (nchunks << 2) + grp; e < n_edges; e += ngrp) {
            long long row = ei64[e];
            long long col = ei64[n_edges + e];
            float4 v = x4[row * 16 + sub];
            asm volatile("red.global.add.v4.f32 [%0], {%1, %2, %3, %4};"
                         :: "l"(&nsum4[col * 16 + sub]),
                            "f"(v.x), "f"(v.y), "f"(v.z), "f"(v.w) : "memory");
        }
    } else {
        for (int c = grp; c < nchunks; c += ngrp) {
            const int e = c * 4;
            int4 rr = *reinterpret_cast<const int4*>(ei32 + e);
            int4 cc = *reinterpret_cast<const int4*>(ei32 + n_edges + e);
            float4 v0 = x4[(long long)rr.x * 16 + sub];
            float4 v1 = x4[(long long)rr.y * 16 + sub];
            float4 v2 = x4[(long long)rr.z * 16 + sub];
            float4 v3 = x4[(long long)rr.w * 16 + sub];
            asm volatile("red.global.add.v4.f32 [%0], {%1, %2, %3, %4};"
                         :: "l"(&nsum4[(long long)cc.x * 16 + sub]),
                            "f"(v0.x), "f"(v0.y), "f"(v0.z), "f"(v0.w) : "memory");
            asm volatile("red.global.add.v4.f32 [%0], {%1, %2, %3, %4};"
                         :: "l"(&nsum4[(long long)cc.y * 16 + sub]),
                            "f"(v1.x), "f"(v1.y), "f"(v1.z), "f"(v1.w) : "memory");
            asm volatile("red.global.add.v4.f32 [%0], {%1, %2, %3, %4};"
                         :: "l"(&nsum4[(long long)cc.z * 16 + sub]),
                            "f"(v2.x), "f"(v2.y), "f"(v2.z), "f"(v2.w) : "memory");
            asm volatile("red.global.add.v4.f32 [%0], {%1, %2, %3, %4};"
                         :: "l"(&nsum4[(long long)cc.w * 16 + sub]),
                            "f"(v3.x), "f"(v3.y), "f"(v3.z), "f"(v3.w) : "memory");
        }
        for (int e = (nchunks << 2) + grp; e < n_edges; e += ngrp) {
            long long row = ei32[e];
            long long col = ei32[n_edges + e];
            float4 v = x4[row * 16 + sub];
            asm volatile("red.global.add.v4.f32 [%0], {%1, %2, %3, %4};"
                         :: "l"(&nsum4[col * 16 + sub]),
                            "f"(v.x), "f"(v.y), "f"(v.z), "f"(v.w) : "memory");
        }
    }
}

// ---------------------------------------------------------------------------
// Kernel 2: mma.sync bf16 (3-pass hi/lo) GEMM + bias + LayerNorm.
// Tile 128 nodes x 64 outs, K=128. A and W^T in SMEM as bf16, split into
// 64-k halves with 128B rows + Swizzle<3,4,3> (conflict-free ldmatrix).
// 3 passes into fp32 accumulators: A_hi*W_hi + A_lo*W_hi + A_hi*W_lo.
// Epilogue: LN per row; rows live in quad lanes -> 2x shfl.xor reduction.
// ---------------------------------------------------------------------------
#define TILE_N 128
#define GTHR   256

// smem layout (bytes): A_hi h0/h1 (2x16KB), A_lo (2x16KB), W_hi (2x8KB), W_lo (2x8KB)
#define SM_AHI  0
#define SM_ALO  32768
#define SM_WHI  65536
#define SM_WLO  81920
#define SM_TOT  98304

__device__ __forceinline__ uint32_t smem_u32(const void* p) {
    uint32_t a;
    asm("{ .reg .u64 t; cvta.to.shared.u64 t, %1; cvt.u32.u64 %0, t; }"
        : "=r"(a) : "l"(p));
    return a;
}
__device__ __forceinline__ uint32_t sw128(uint32_t o) { return o ^ ((o >> 3) & 0x70); }

__device__ __forceinline__ unsigned pack_bf16x2(float lo_f, float hi_f) {
    __nv_bfloat16 a = __float2bfloat16(lo_f);
    __nv_bfloat16 c = __float2bfloat16(hi_f);
    return ((unsigned)__bfloat16_as_ushort(c) << 16) | (unsigned)__bfloat16_as_ushort(a);
}

__device__ __forceinline__ void ldmx4(uint32_t addr, uint32_t* r) {
    asm volatile("ldmatrix.sync.aligned.m8n8.x4.shared.b16 {%0,%1,%2,%3}, [%4];"
                 : "=r"(r[0]), "=r"(r[1]), "=r"(r[2]), "=r"(r[3]) : "r"(addr));
}
__device__ __forceinline__ void mma_bf16(float* c, const uint32_t* a,
                                         uint32_t b0, uint32_t b1) {
    asm volatile(
        "mma.sync.aligned.m16n8k16.row.col.f32.bf16.bf16.f32 "
        "{%0,%1,%2,%3}, {%4,%5,%6,%7}, {%8,%9}, {%0,%1,%2,%3};"
        : "+f"(c[0]), "+f"(c[1]), "+f"(c[2]), "+f"(c[3])
        : "r"(a[0]), "r"(a[1]), "r"(a[2]), "r"(a[3]), "r"(b0), "r"(b1));
}

__global__ void __launch_bounds__(GTHR, 2) gemm_mma_ln_kernel(
    const float4* __restrict__ x4,
    const float4* __restrict__ W4,   // [128][16] float4  (W row-major [128][64])
    const float*  __restrict__ b,
    const float*  __restrict__ gamma,
    const float*  __restrict__ beta,
    float2* __restrict__ out2,
    int n_nodes) {

    extern __shared__ char smem[];
    const uint32_t sbase = smem_u32(smem);
    const int tid = threadIdx.x;
    const int wid = tid >> 5;
    const int lid = tid & 31;
    const int node_base = blockIdx.x * TILE_N;

    // ---- stage A (hi/lo bf16, k-major, SW128 halves) ----
    {
        const float4* nsum4 = reinterpret_cast<const float4*>(g_nsum);
        #pragma unroll
        for (int it = 0; it < 16; it++) {
            int idx = it * GTHR + tid;     // 0..4095
            int r = idx & 31;              // k-quad 0..31  (lanes consecutive in k)
            int n = idx >> 5;              // node row 0..127
            int gn = node_base + n;
            float4 v = make_float4(0.f, 0.f, 0.f, 0.f);
            if (gn < n_nodes)
                v = (r < 16) ? x4[(long long)gn * 16 + r]
                             : nsum4[(long long)gn * 16 + (r - 16)];
            // hi/lo split
            float hx = __bfloat162float(__float2bfloat16(v.x));
            float hy = __bfloat162float(__float2bfloat16(v.y));
            float hz = __bfloat162float(__float2bfloat16(v.z));
            float hw = __bfloat162float(__float2bfloat16(v.w));
            uint2 hi = make_uint2(pack_bf16x2(hx, hy), pack_bf16x2(hz, hw));
            uint2 lo = make_uint2(pack_bf16x2(v.x - hx, v.y - hy),
                                  pack_bf16x2(v.z - hz, v.w - hw));
            int h = r >> 4;                         // k-half
            uint32_t off = sw128((uint32_t)(n * 128 + (r & 15) * 8));
            *reinterpret_cast<uint2*>(smem + SM_AHI + h * 16384 + off) = hi;
            *reinterpret_cast<uint2*>(smem + SM_ALO + h * 16384 + off) = lo;
        }
    }
    // ---- stage W^T (hi/lo bf16) : Wsh[n][k] from W[k][n] ----
    {
        #pragma unroll
        for (int it = 0; it < 8; it++) {
            int idx = it * GTHR + tid;     // 0..2047
            int k = idx >> 4;              // 0..127
            int n4 = idx & 15;
            float4 w = W4[idx];            // coalesced: 4 consecutive n for this k
            const float ww[4] = {w.x, w.y, w.z, w.w};
            int h = k >> 6;
            int klocal = k & 63;
            #pragma unroll
            for (int j = 0; j < 4; j++) {
                int n = 4 * n4 + j;
                float hv = __bfloat162float(__float2bfloat16(ww[j]));
                uint32_t off = sw128((uint32_t)(n * 128 + klocal * 2));
                *reinterpret_cast<__nv_bfloat16*>(smem + SM_WHI + h * 8192 + off) =
                    __float2bfloat16(ww[j]);
                *reinterpret_cast<__nv_bfloat16*>(smem + SM_WLO + h * 8192 + off) =
                    __float2bfloat16(ww[j] - hv);
            }
        }
    }
    __syncthreads();

    // ---- mainloop: warp w owns rows 16w..16w+15, all 64 cols ----
    const int m_base = wid * 16;
    float acc[8][4];
    #pragma unroll
    for (int nt = 0; nt < 8; nt++)
        #pragma unroll
        for (int j = 0; j < 4; j++) acc[nt][j] = 0.f;

    const int l15 = lid & 15;
    const int lh  = lid >> 4;

    #pragma unroll 1
    for (int pass = 0; pass < 3; pass++) {
        const uint32_t aMat = sbase + ((pass == 1) ? SM_ALO : SM_AHI);
        const uint32_t wMat = sbase + ((pass == 2) ? SM_WLO : SM_WHI);
        #pragma unroll
        for (int s = 0; s < 8; s++) {
            const int h = s >> 2;
            const int klb = (s & 3) * 32;          // byte offset of k within half
            uint32_t a[4];
            {
                uint32_t off = sw128((uint32_t)((m_base + l15) * 128 + klb + lh * 16));
                ldmx4(aMat + h * 16384 + off, a);
            }
            uint32_t bf[4][4];
            #pragma unroll
            for (int q = 0; q < 4; q++) {
                uint32_t off = sw128((uint32_t)((q * 16 + l15) * 128 + klb + lh * 16));
                ldmx4(wMat + h * 8192 + off, bf[q]);
            }
            #pragma unroll
            for (int nt = 0; nt < 8; nt++) {
                const int q = nt >> 1;
                uint32_t b0 = (nt & 1) ? bf[q][1] : bf[q][0];
                uint32_t b1 = (nt & 1) ? bf[q][3] : bf[q][2];
                mma_bf16(acc[nt], a, b0, b1);
            }
        }
    }

    // ---- epilogue: bias + LayerNorm + store ----
    // D m16n8 frag: c0,c1 -> row qr, cols 8nt+2qc,+1 ; c2,c3 -> row qr+8
    const int qr = lid >> 2;
    const int qc = lid & 3;
    const float2* b2 = reinterpret_cast<const float2*>(b);
    const float2* g2 = reinterpret_cast<const float2*>(gamma);
    const float2* e2 = reinterpret_cast<const float2*>(beta);

    float s0 = 0.f, ss0 = 0.f, s1 = 0.f, ss1 = 0.f;
    #pragma unroll
    for (int nt = 0; nt < 8; nt++) {
        float2 bb = __ldg(b2 + 4 * nt + qc);
        acc[nt][0] += bb.x;  acc[nt][1] += bb.y;
        acc[nt][2] += bb.x;  acc[nt][3] += bb.y;
        s0  += acc[nt][0] + acc[nt][1];
        ss0 += acc[nt][0] * acc[nt][0] + acc[nt][1] * acc[nt][1];
        s1  += acc[nt][2] + acc[nt][3];
        ss1 += acc[nt][2] * acc[nt][2] + acc[nt][3] * acc[nt][3];
    }
    #pragma unroll
    for (int m = 1; m < 4; m <<= 1) {
        s0  += __shfl_xor_sync(0xFFFFFFFFu, s0,  m);
        ss0 += __shfl_xor_sync(0xFFFFFFFFu, ss0, m);
        s1  += __shfl_xor_sync(0xFFFFFFFFu, s1,  m);
        ss1 += __shfl_xor_sync(0xFFFFFFFFu, ss1, m);
    }
    const float inv64 = 1.0f / 64.0f;
    float mu0 = s0 * inv64, var0 = ss0 * inv64 - mu0 * mu0;
    float mu1 = s1 * inv64, var1 = ss1 * inv64 - mu1 * mu1;
    float rs0 = rsqrtf(var0 + LN_EPS);
    float rs1 = rsqrtf(var1 + LN_EPS);

    const int gr0 = node_base + m_base + qr;
    const int gr1 = gr0 + 8;
    #pragma unroll
    for (int nt = 0; nt < 8; nt++) {
        float2 gg = __ldg(g2 + 4 * nt + qc);
        float2 ee = __ldg(e2 + 4 * nt + qc);
        if (gr0 < n_nodes) {
            float2 o;
            o.x = (acc[nt][0] - mu0) * rs0 * gg.x + ee.x;
            o.y = (acc[nt][1] - mu0) * rs0 * gg.y + ee.y;
            out2[(long long)gr0 * 32 + 4 * nt + qc] = o;
        }
        if (gr1 < n_nodes) {
            float2 o;
            o.x = (acc[nt][2] - mu1) * rs1 * gg.x + ee.x;
            o.y = (acc[nt][3] - mu1) * rs1 * gg.y + ee.y;
            out2[(long long)gr1 * 32 + 4 * nt + qc] = o;
        }
    }
}

// ---------------------------------------------------------------------------
// launch
// ---------------------------------------------------------------------------
extern "C" void kernel_launch(void* const* d_in, const int* in_sizes, int n_in,
                              void* d_out, int out_size) {
    const float* x     = (const float*)d_in[0];
    const void*  ei    = d_in[1];
    const float* W     = (const float*)d_in[2];
    const float* b     = (const float*)d_in[3];
    const float* gamma = (const float*)d_in[4];
    const float* beta  = (const float*)d_in[5];
    float* out = (float*)d_out;

    const int n_nodes = in_sizes[0] / D;      // 100000
    const int n_edges = in_sizes[1] / 2;      // 1000000

    static void* nsum_ptr = nullptr;
    if (!nsum_ptr) {
        cudaGetSymbolAddress(&nsum_ptr, g_nsum);
        cudaFuncSetAttribute(gemm_mma_ln_kernel,
                             cudaFuncAttributeMaxDynamicSharedMemorySize, SM_TOT);
    }

    // 0: zero accumulator
    cudaMemsetAsync(nsum_ptr, 0, (size_t)n_nodes * D * sizeof(float), 0);

    // 1: scatter
    scatter_kernel<<<2368, 256>>>((const float4*)x, ei, n_edges, n_nodes);

    // 2: tensor-core bf16 (3-pass) GEMM + LayerNorm
    int gemm_blocks = (n_nodes + TILE_N - 1) / TILE_N;
    gemm_mma_ln_kernel<<<gemm_blocks, GTHR, SM_TOT>>>(
        (const float4*)x, (const float4*)W, b, gamma, beta,
        (float2*)out, n_nodes);
}